// round 8
// baseline (speedup 1.0000x reference)
#include <cuda_runtime.h>
#include <cstdint>

// SwappingCorruption: out[i,j] = mask[i,j] ? x[i, perm[i,j]] : x[i,j]
// B=16384 rows, F=2048 cols, fp32. mask is int32 (0/1), perm is int32
// row-local indices. Gather is strictly within-row (8 KB): stage the row in
// shared memory, serve identity + gather from SMEM (x read from HBM once).
// Skip the perm int4 load when all 4 mask words are zero (p ≈ 0.9^4 ≈ 0.66).

static constexpr int N_FEAT  = 2048;
static constexpr int THREADS = 256;
static constexpr int VEC_PER_ROW = N_FEAT / 4;               // 512 float4 per row
static constexpr int VEC_PER_THREAD = VEC_PER_ROW / THREADS; // 2

__global__ __launch_bounds__(THREADS)
void swap_corruption_kernel(const float* __restrict__ x,
                            const int*   __restrict__ mask,
                            const int*   __restrict__ perm,
                            float* __restrict__ out)
{
    __shared__ float row[N_FEAT];

    const size_t base = (size_t)blockIdx.x * N_FEAT;
    const float4* xr  = reinterpret_cast<const float4*>(x + base);
    float4*       owr = reinterpret_cast<float4*>(out + base);
    const int4*   mr  = reinterpret_cast<const int4*>(mask + base);
    const int4*   pr  = reinterpret_cast<const int4*>(perm + base);
    float4* srow4 = reinterpret_cast<float4*>(row);

    const int t = threadIdx.x;

    // Stage the full row into SMEM (coalesced float4 loads, MLP=2 per thread).
    #pragma unroll
    for (int i = 0; i < VEC_PER_THREAD; ++i) {
        const int idx = t + i * THREADS;
        srow4[idx] = xr[idx];
    }
    __syncthreads();

    #pragma unroll
    for (int i = 0; i < VEC_PER_THREAD; ++i) {
        const int idx = t + i * THREADS;
        float4 v = srow4[idx];          // identity values from SMEM (no 2nd HBM read)
        const int4 m = mr[idx];         // 4 int32 mask words
        if (m.x | m.y | m.z | m.w) {    // skip perm load for all-false quads (~66%)
            const int4 p = pr[idx];
            if (m.x) v.x = row[p.x];
            if (m.y) v.y = row[p.y];
            if (m.z) v.z = row[p.z];
            if (m.w) v.w = row[p.w];
        }
        owr[idx] = v;
    }
}

extern "C" void kernel_launch(void* const* d_in, const int* in_sizes, int n_in,
                              void* d_out, int out_size)
{
    // metadata order: x (float32), swap_mask (int32 0/1), perm (int32)
    const float* x    = (const float*)d_in[0];
    const int*   mask = (const int*)d_in[1];
    const int*   perm = (const int*)d_in[2];
    float*       out  = (float*)d_out;

    const int batch = in_sizes[0] / N_FEAT;  // 16384
    swap_corruption_kernel<<<batch, THREADS>>>(x, mask, perm, out);
}